// round 10
// baseline (speedup 1.0000x reference)
#include <cuda_runtime.h>
#include <stdint.h>

// PatchMasker: out = concat(where(mask[t], 0, x_dist),
//                           where(mask[t], 0, x_tre),
//                           where(mask[t], 0, x_sea))
// x_* = (B=256, T=512, F=256) fp32, mask = (T=512,) int32.
//
// Converged HBM-streaming kernel (~6.3 TB/s chip cap, minimal traffic:
// 403 MB writes + kept-row-only reads). R9 -> R10: test the one untried
// sm_10x lever — 256-bit global accesses (ld/st.global.v8.f32, LDG.E.256/
// STG.256) to halve L1tex wavefronts per byte and lengthen DRAM bursts.
// Same structure as the converged kernel otherwise: one tensor per
// blockIdx.y, warp-contiguous indices, predicated loads, .cs policy.

#define B_DIM 256
#define T_DIM 512
#define F_DIM 256

#define N8_PER ((long)B_DIM * T_DIM * F_DIM / 8)  // f32x8 per tensor = 2^22
#define ROW_SHIFT 5                               // 32 f32x8 per (b,t) row
#define T_MASK (T_DIM - 1)
#define BLK 256
#define C_PER_THREAD 2
#define C_PER_BLOCK (C_PER_THREAD * BLK)          // 512

struct alignas(32) f32x8 { float v[8]; };

__device__ __forceinline__ void ldcs_v8(f32x8& r, const f32x8* p)
{
    asm volatile(
        "ld.global.cs.v8.f32 {%0,%1,%2,%3,%4,%5,%6,%7}, [%8];"
        : "=f"(r.v[0]), "=f"(r.v[1]), "=f"(r.v[2]), "=f"(r.v[3]),
          "=f"(r.v[4]), "=f"(r.v[5]), "=f"(r.v[6]), "=f"(r.v[7])
        : "l"(p));
}

__device__ __forceinline__ void stcs_v8(f32x8* p, const f32x8& r)
{
    asm volatile(
        "st.global.cs.v8.f32 [%0], {%1,%2,%3,%4,%5,%6,%7,%8};"
        :: "l"(p),
           "f"(r.v[0]), "f"(r.v[1]), "f"(r.v[2]), "f"(r.v[3]),
           "f"(r.v[4]), "f"(r.v[5]), "f"(r.v[6]), "f"(r.v[7])
        : "memory");
}

__global__ void __launch_bounds__(BLK, 8)
patch_masker_kernel(const f32x8* __restrict__ xd,
                    const f32x8* __restrict__ xt,
                    const f32x8* __restrict__ xs,
                    const int* __restrict__ mask,
                    f32x8* __restrict__ out)
{
    // One tensor per blockIdx.y: 1 read + 1 write stream per block.
    const f32x8* __restrict__ src =
        (blockIdx.y == 0) ? xd : (blockIdx.y == 1) ? xt : xs;
    f32x8* __restrict__ dst = out + (long)blockIdx.y * N8_PER;

    long base = (long)blockIdx.x * C_PER_BLOCK + threadIdx.x;

    f32x8 z;
#pragma unroll
    for (int e = 0; e < 8; e++) z.v[e] = 0.f;

    long idx[C_PER_THREAD];
    bool k[C_PER_THREAD];
    f32x8 val[C_PER_THREAD];

#pragma unroll
    for (int j = 0; j < C_PER_THREAD; j++) {
        idx[j] = base + (long)j * BLK;               // warp-contiguous
        int t = (int)((idx[j] >> ROW_SHIFT) & T_MASK);
        k[j] = (mask[t] == 0);                       // 2 KB table, L1-resident
        val[j] = z;
    }

    // Predicated 256-bit loads: masked rows generate zero read traffic.
#pragma unroll
    for (int j = 0; j < C_PER_THREAD; j++) {
        if (k[j]) ldcs_v8(val[j], &src[idx[j]]);
    }

#pragma unroll
    for (int j = 0; j < C_PER_THREAD; j++) {
        stcs_v8(&dst[idx[j]], val[j]);
    }
}

extern "C" void kernel_launch(void* const* d_in, const int* in_sizes, int n_in,
                              void* d_out, int out_size)
{
    const f32x8* xd = (const f32x8*)d_in[0];
    const f32x8* xt = (const f32x8*)d_in[1];
    const f32x8* xs = (const f32x8*)d_in[2];
    const int* mask = (const int*)d_in[3];
    f32x8* out = (f32x8*)d_out;

    dim3 grid((unsigned)(N8_PER / C_PER_BLOCK), 3);  // (8192, 3), exact
    patch_masker_kernel<<<grid, BLK>>>(xd, xt, xs, mask, out);
}

// round 11
// speedup vs baseline: 1.0023x; 1.0023x over previous
#include <cuda_runtime.h>
#include <stdint.h>

// PatchMasker: out = concat(where(mask[t], 0, x_dist),
//                           where(mask[t], 0, x_tre),
//                           where(mask[t], 0, x_sea))
// x_* = (B=256, T=512, F=256) fp32, mask = (T=512,) int32.
//
// FINAL (converged at the roofline): pure HBM-streaming kernel pinned at the
// B300 chip-level memory throughput cap (~6.3 TB/s measured, path-independent).
// Traffic is information-theoretically minimal: all 403 MB of output written,
// input reads predicated off for masked rows (~40% of T), ~587 MB total.
//
// Exhaustively tested alternatives (all with ncu evidence):
//   MLP 3/4/6 per thread ......... identical (+-0.3%)
//   128-bit vs 256-bit accesses .. identical (+-1%)
//   stream layouts ............... identical
//   strided pairs ................ -19% (sector waste)
//   persistent CTAs .............. -21% (occupancy/L1tex-queue underfill)
//
// Structure: one tensor per blockIdx.y (1 read + 1 write stream per block),
// 4 warp-coalesced float4 per thread, front-batched predicated loads,
// streaming (.cs) cache policy.

#define B_DIM 256
#define T_DIM 512
#define F_DIM 256

#define N4_PER ((long)B_DIM * T_DIM * F_DIM / 4)  // float4 per tensor = 2^23
#define ROW_SHIFT 6                               // 64 float4 per (b,t) row
#define T_MASK (T_DIM - 1)
#define BLK 256
#define F4_PER_THREAD 4
#define F4_PER_BLOCK (F4_PER_THREAD * BLK)        // 1024

__global__ void __launch_bounds__(BLK, 8)
patch_masker_kernel(const float4* __restrict__ xd,
                    const float4* __restrict__ xt,
                    const float4* __restrict__ xs,
                    const int* __restrict__ mask,
                    float4* __restrict__ out)
{
    // One tensor per blockIdx.y: exactly 1 read + 1 write stream per block.
    const float4* __restrict__ src =
        (blockIdx.y == 0) ? xd : (blockIdx.y == 1) ? xt : xs;
    float4* __restrict__ dst = out + (long)blockIdx.y * N4_PER;

    long base = (long)blockIdx.x * F4_PER_BLOCK + threadIdx.x;

    const float4 z = make_float4(0.f, 0.f, 0.f, 0.f);
    float4 v[F4_PER_THREAD];
    bool  k[F4_PER_THREAD];
    long  idx[F4_PER_THREAD];

#pragma unroll
    for (int j = 0; j < F4_PER_THREAD; j++) {
        idx[j] = base + (long)j * BLK;               // warp-contiguous
        int t = (int)((idx[j] >> ROW_SHIFT) & T_MASK);
        k[j] = (mask[t] == 0);                       // 2 KB table, L1-resident
        v[j] = z;
    }

    // Front-batched independent predicated loads (up to 4 LDG.128 in flight);
    // masked rows generate zero read traffic.
#pragma unroll
    for (int j = 0; j < F4_PER_THREAD; j++) {
        if (k[j]) v[j] = __ldcs(&src[idx[j]]);
    }

#pragma unroll
    for (int j = 0; j < F4_PER_THREAD; j++) {
        __stcs(&dst[idx[j]], v[j]);
    }
}

extern "C" void kernel_launch(void* const* d_in, const int* in_sizes, int n_in,
                              void* d_out, int out_size)
{
    const float4* xd = (const float4*)d_in[0];
    const float4* xt = (const float4*)d_in[1];
    const float4* xs = (const float4*)d_in[2];
    const int* mask  = (const int*)d_in[3];
    float4* out = (float4*)d_out;

    dim3 grid((unsigned)(N4_PER / F4_PER_BLOCK), 3);  // (8192, 3), exact
    patch_masker_kernel<<<grid, BLK>>>(xd, xt, xs, mask, out);
}

// round 12
// speedup vs baseline: 1.0033x; 1.0010x over previous
#include <cuda_runtime.h>
#include <stdint.h>

// PatchMasker: out = concat(where(mask[t], 0, x_dist),
//                           where(mask[t], 0, x_tre),
//                           where(mask[t], 0, x_sea))
// x_* = (B=256, T=512, F=256) fp32, mask = (T=512,) int32.
//
// FINAL (converged at the roofline): pure HBM-streaming kernel pinned at the
// B300 chip-level memory throughput cap (6.24-6.38 TB/s across runs; the
// spread is the HW's own run-to-run variation band, not code-dependent).
// Traffic is information-theoretically minimal: all 403 MB of output written
// (d_out is poisoned, zeros must be materialized), input reads predicated off
// for masked rows (~40% of T), ~587 MB total.
//
// Exhaustively tested alternatives (each with an ncu-verified post-mortem):
//   MLP 3/4/6 per thread ......... identical (+-0.3%)
//   128-bit vs 256-bit accesses .. identical (+-1%)   [L1 never the binder]
//   stream layouts (6 vs 2/blk) .. identical
//   strided pairs ................ -19% (32B-sector waste)
//   persistent CTAs .............. -21% (occupancy / L1tex-queue underfill)
//
// Structure: one tensor per blockIdx.y (1 read + 1 write stream per block),
// 4 warp-coalesced float4 per thread, front-batched predicated loads,
// streaming (.cs) cache policy.

#define B_DIM 256
#define T_DIM 512
#define F_DIM 256

#define N4_PER ((long)B_DIM * T_DIM * F_DIM / 4)  // float4 per tensor = 2^23
#define ROW_SHIFT 6                               // 64 float4 per (b,t) row
#define T_MASK (T_DIM - 1)
#define BLK 256
#define F4_PER_THREAD 4
#define F4_PER_BLOCK (F4_PER_THREAD * BLK)        // 1024

__global__ void __launch_bounds__(BLK, 8)
patch_masker_kernel(const float4* __restrict__ xd,
                    const float4* __restrict__ xt,
                    const float4* __restrict__ xs,
                    const int* __restrict__ mask,
                    float4* __restrict__ out)
{
    // One tensor per blockIdx.y: exactly 1 read + 1 write stream per block.
    const float4* __restrict__ src =
        (blockIdx.y == 0) ? xd : (blockIdx.y == 1) ? xt : xs;
    float4* __restrict__ dst = out + (long)blockIdx.y * N4_PER;

    long base = (long)blockIdx.x * F4_PER_BLOCK + threadIdx.x;

    const float4 z = make_float4(0.f, 0.f, 0.f, 0.f);
    float4 v[F4_PER_THREAD];
    bool  k[F4_PER_THREAD];
    long  idx[F4_PER_THREAD];

#pragma unroll
    for (int j = 0; j < F4_PER_THREAD; j++) {
        idx[j] = base + (long)j * BLK;               // warp-contiguous
        int t = (int)((idx[j] >> ROW_SHIFT) & T_MASK);
        k[j] = (mask[t] == 0);                       // 2 KB table, L1-resident
        v[j] = z;
    }

    // Front-batched independent predicated loads (up to 4 LDG.128 in flight);
    // masked rows generate zero read traffic.
#pragma unroll
    for (int j = 0; j < F4_PER_THREAD; j++) {
        if (k[j]) v[j] = __ldcs(&src[idx[j]]);
    }

#pragma unroll
    for (int j = 0; j < F4_PER_THREAD; j++) {
        __stcs(&dst[idx[j]], v[j]);
    }
}

extern "C" void kernel_launch(void* const* d_in, const int* in_sizes, int n_in,
                              void* d_out, int out_size)
{
    const float4* xd = (const float4*)d_in[0];
    const float4* xt = (const float4*)d_in[1];
    const float4* xs = (const float4*)d_in[2];
    const int* mask  = (const int*)d_in[3];
    float4* out = (float4*)d_out;

    dim3 grid((unsigned)(N4_PER / F4_PER_BLOCK), 3);  // (8192, 3), exact
    patch_masker_kernel<<<grid, BLK>>>(xd, xt, xs, mask, out);
}